// round 1
// baseline (speedup 1.0000x reference)
#include <cuda_runtime.h>

// Conv1d over W (K=3, pad=1) + roll(+1) on H.
// x: (128,128,28,28) f32, w: (32,128,3) f32 -> out: (128,32,28,28) f32.
//
// Strategy: fp32x2 packed FMA (sm_103a FFMA2) register-tiled kernel.
//  - weights pre-transposed to wT[ci][k][co] so cout-pairs load as ulonglong2
//  - x tile in smem with halo (zero pad), block = (batch, 4 h-rows)
//  - thread: 8 cout-pairs x 4 w-positions accumulators, 4-way ci split
//    reduced via warp shuffle (split lives in lane bits 0..1)

typedef unsigned long long ull;

__device__ __align__(16) float g_wT[128 * 3 * 32];   // [ci][k][co]

__device__ __forceinline__ ull fma2(ull a, ull b, ull c) {
    ull d;
    asm("fma.rn.f32x2 %0, %1, %2, %3;" : "=l"(d) : "l"(a), "l"(b), "l"(c));
    return d;
}
__device__ __forceinline__ ull add2(ull a, ull b) {
    ull d;
    asm("add.rn.f32x2 %0, %1, %2;" : "=l"(d) : "l"(a), "l"(b));
    return d;
}
__device__ __forceinline__ ull dup2(float f) {
    ull d;
    unsigned u = __float_as_uint(f);
    asm("mov.b64 %0, {%1, %2};" : "=l"(d) : "r"(u), "r"(u));
    return d;
}
__device__ __forceinline__ void unpack2(ull v, float& lo, float& hi) {
    unsigned a, b;
    asm("mov.b64 {%0, %1}, %2;" : "=r"(a), "=r"(b) : "l"(v));
    lo = __uint_as_float(a);
    hi = __uint_as_float(b);
}

// w global layout [co][ci][k] (co*384 + ci*3 + k) -> wT[(ci*3+k)*32 + co]
__global__ void wT_kernel(const float* __restrict__ w) {
    int i = blockIdx.x * 256 + threadIdx.x;
    if (i < 12288) {
        int co = i / 384;
        int r  = i % 384;
        g_wT[r * 32 + co] = w[i];
    }
}

constexpr int HB = 4;     // h-rows per block
constexpr int NT = 224;   // threads per block

__global__ __launch_bounds__(NT, 2)
void conv_kernel(const float* __restrict__ x, float* __restrict__ out) {
    extern __shared__ float smx[];   // [128][HB][32], col 0 = x[-1]=0, col 29 = x[28]=0
    const int b  = blockIdx.y;
    const int h0 = blockIdx.x * HB;
    const int tid = threadIdx.x;

    // halo zeros (cols 0 and 29; 30/31 never read)
    for (int i = tid; i < 128 * HB; i += NT) {
        smx[i * 32]      = 0.f;
        smx[i * 32 + 29] = 0.f;
    }
    // x tile: x[b, ci, h0+hh, w] -> smx[(ci*HB+hh)*32 + 1 + w]
    const float* xg = x + (size_t)b * 128 * 28 * 28;
    for (int i = tid; i < 128 * HB * 28; i += NT) {   // 14336/224 = 64 iters
        int ci = i / (HB * 28);
        int r  = i % (HB * 28);
        int hh = r / 28;
        int w_ = r % 28;
        smx[(ci * HB + hh) * 32 + 1 + w_] = xg[(ci * 28 + h0 + hh) * 28 + w_];
    }
    __syncthreads();

    const int s    = tid & 3;          // ci-split (lane bits 0..1 -> shfl reduce)
    const int cg   = (tid >> 2) & 1;   // cout half: couts [16*cg, 16*cg+16)
    const int posg = tid >> 3;         // 0..27
    const int hh   = posg / 7;
    const int w0   = (posg % 7) * 4;

    ull acc[8][4];
#pragma unroll
    for (int j = 0; j < 8; j++)
#pragma unroll
        for (int p = 0; p < 4; p++) acc[j][p] = 0ull;

    const float* xr = smx + ((s * 32) * HB + hh) * 32 + w0;   // idx w0 = x[w0-1]
    const float* wr = g_wT + (s * 32) * 96 + cg * 16;

#pragma unroll 1
    for (int ci = 0; ci < 32; ci++) {
        float4 xa = *(const float4*)xr;         // x[w0-1 .. w0+2]
        float2 xb = *(const float2*)(xr + 4);   // x[w0+3], x[w0+4]
        ull xd[6] = { dup2(xa.x), dup2(xa.y), dup2(xa.z),
                      dup2(xa.w), dup2(xb.x), dup2(xb.y) };
#pragma unroll
        for (int k = 0; k < 3; k++) {
            const ulonglong2* wk = (const ulonglong2*)(wr + k * 32);
#pragma unroll
            for (int q = 0; q < 4; q++) {
                ulonglong2 wv = wk[q];   // couts 16cg+4q .. +4q+3 as 2 pairs
#pragma unroll
                for (int p = 0; p < 4; p++) {
                    acc[2 * q    ][p] = fma2(wv.x, xd[p + k], acc[2 * q    ][p]);
                    acc[2 * q + 1][p] = fma2(wv.y, xd[p + k], acc[2 * q + 1][p]);
                }
            }
        }
        xr += HB * 32;
        wr += 96;
    }

    // reduce the 4-way ci split across lanes (xor 1, xor 2)
#pragma unroll
    for (int j = 0; j < 8; j++)
#pragma unroll
        for (int p = 0; p < 4; p++) {
            ull v = acc[j][p];
            v = add2(v, __shfl_xor_sync(0xffffffffu, v, 1));
            v = add2(v, __shfl_xor_sync(0xffffffffu, v, 2));
            acc[j][p] = v;
        }

    if (s == 0) {
        int hp = (h0 + hh + 1) % 28;   // roll(+1) along H
#pragma unroll
        for (int j = 0; j < 8; j++) {
            int co = cg * 16 + 2 * j;
            float lo[4], hi[4];
#pragma unroll
            for (int p = 0; p < 4; p++) unpack2(acc[j][p], lo[p], hi[p]);
            float* o0 = out + (((size_t)b * 32 + co) * 28 + hp) * 28 + w0;
            float* o1 = o0 + 784;
            *(float4*)o0 = make_float4(lo[0], lo[1], lo[2], lo[3]);
            *(float4*)o1 = make_float4(hi[0], hi[1], hi[2], hi[3]);
        }
    }
}

extern "C" void kernel_launch(void* const* d_in, const int* in_sizes, int n_in,
                              void* d_out, int out_size) {
    const float* x = (const float*)d_in[0];
    const float* w = (const float*)d_in[1];
    float* out = (float*)d_out;

    cudaFuncSetAttribute(conv_kernel,
                         cudaFuncAttributeMaxDynamicSharedMemorySize,
                         128 * HB * 32 * (int)sizeof(float));

    wT_kernel<<<48, 256>>>(w);
    conv_kernel<<<dim3(7, 128), NT, 128 * HB * 32 * sizeof(float)>>>(x, out);
}

// round 2
// speedup vs baseline: 1.7983x; 1.7983x over previous
#include <cuda_runtime.h>

// Conv1d over W (K=3, pad=1) + roll(+1) on H.
// x: (128,128,28,28) f32, w: (32,128,3) f32 -> out: (128,32,28,28) f32.
//
// Round 2: warp-uniform weight loads. The (ci-split s, cout-half cg) pair
// lives in the WARP index (8 warps = 4s x 2cg), so every weight LDG.128 is
// the same address across the warp -> 1 L1 wavefront instead of ~8.
// Lane = position (hh in 0..3, w-group of 4). ci-split partials reduced
// through shared memory once per block.

typedef unsigned long long ull;

__device__ __align__(16) float g_wT[128 * 3 * 32];   // [ci][k][co]

__device__ __forceinline__ ull fma2(ull a, ull b, ull c) {
    ull d;
    asm("fma.rn.f32x2 %0, %1, %2, %3;" : "=l"(d) : "l"(a), "l"(b), "l"(c));
    return d;
}
__device__ __forceinline__ ull add2(ull a, ull b) {
    ull d;
    asm("add.rn.f32x2 %0, %1, %2;" : "=l"(d) : "l"(a), "l"(b));
    return d;
}
__device__ __forceinline__ ull dup2(float f) {
    ull d;
    unsigned u = __float_as_uint(f);
    asm("mov.b64 %0, {%1, %2};" : "=l"(d) : "r"(u), "r"(u));
    return d;
}
__device__ __forceinline__ void unpack2(ull v, float& lo, float& hi) {
    unsigned a, b;
    asm("mov.b64 {%0, %1}, %2;" : "=r"(a), "=r"(b) : "l"(v));
    lo = __uint_as_float(a);
    hi = __uint_as_float(b);
}

// w global layout [co][ci][k] (co*384 + ci*3 + k) -> wT[(ci*3+k)*32 + co]
__global__ void wT_kernel(const float* __restrict__ w) {
    int i = blockIdx.x * 256 + threadIdx.x;
    if (i < 12288) {
        int co = i / 384;
        int r  = i % 384;
        g_wT[r * 32 + co] = w[i];
    }
}

constexpr int HB = 4;     // h-rows per block
constexpr int NT = 256;   // 8 warps: 4 ci-splits x 2 cout-halves
constexpr int RS = 36;    // smem row stride in floats (128B+16B -> no bank dup across rows)
constexpr int SMEM_BYTES = 128 * HB * RS * 4;   // 73728

__global__ __launch_bounds__(NT, 2)
void conv_kernel(const float* __restrict__ x, float* __restrict__ out) {
    extern __shared__ __align__(16) float smx[];   // [128*HB][RS]; col0 = x[-1]=0, col29 = x[28]=0
    const int b   = blockIdx.y;
    const int h0  = blockIdx.x * HB;
    const int tid = threadIdx.x;
    const int warp = tid >> 5;
    const int lane = tid & 31;

    // halo zeros
    for (int i = tid; i < 128 * HB; i += NT) {
        smx[i * RS]      = 0.f;
        smx[i * RS + 29] = 0.f;
    }
    // x tile: x[b, ci, h0+hh, w] -> smx[(ci*HB+hh)*RS + 1 + w]
    const float* xg = x + (size_t)b * 128 * 28 * 28;
    for (int i = tid; i < 128 * HB * 28; i += NT) {   // 56 iters
        int ci = i / (HB * 28);
        int r  = i % (HB * 28);
        int hh = r / 28;
        int w_ = r % 28;
        smx[(ci * HB + hh) * RS + 1 + w_] = xg[(ci * 28 + h0 + hh) * 28 + w_];
    }
    __syncthreads();

    const int s  = warp & 3;          // ci-split: chunk [32*s, 32*s+32)  (warp-uniform)
    const int cg = warp >> 2;         // cout half: [16*cg, 16*cg+16)     (warp-uniform)
    const bool active = lane < 28;
    const int li = active ? lane : 0;
    const int hh = li / 7;
    const int w0 = (li % 7) * 4;

    ull acc[8][4];
#pragma unroll
    for (int j = 0; j < 8; j++)
#pragma unroll
        for (int p = 0; p < 4; p++) acc[j][p] = 0ull;

    const float* xr = smx + ((s * 32) * HB + hh) * RS + w0;   // idx w0 = x[w0-1]
    const float* wr = g_wT + (s * 32) * 96 + cg * 16;         // warp-uniform address

#pragma unroll 2
    for (int ci = 0; ci < 32; ci++) {
        float4 xa = *(const float4*)xr;         // x[w0-1 .. w0+2]
        float2 xb = *(const float2*)(xr + 4);   // x[w0+3], x[w0+4]
        ull xd[6] = { dup2(xa.x), dup2(xa.y), dup2(xa.z),
                      dup2(xa.w), dup2(xb.x), dup2(xb.y) };
#pragma unroll
        for (int k = 0; k < 3; k++) {
            const ulonglong2* wk = (const ulonglong2*)(wr + k * 32);
#pragma unroll
            for (int q = 0; q < 4; q++) {
                ulonglong2 wv = wk[q];   // couts 16cg+4q .. +4q+3 (uniform -> broadcast)
#pragma unroll
                for (int p = 0; p < 4; p++) {
                    acc[2 * q    ][p] = fma2(wv.x, xd[p + k], acc[2 * q    ][p]);
                    acc[2 * q + 1][p] = fma2(wv.y, xd[p + k], acc[2 * q + 1][p]);
                }
            }
        }
        xr += HB * RS;
        wr += 96;
    }

    // cross-warp reduction of the 4-way ci split through smem (tile is dead now)
    __syncthreads();
    ull* part = (ull*)smx;   // [3][2][28][32] ull = 43008 B <= 72KB
    if (s > 0 && active) {
        ull* dst = part + (((s - 1) * 2 + cg) * 28 + li) * 32;
#pragma unroll
        for (int j = 0; j < 8; j++)
#pragma unroll
            for (int p = 0; p < 4; p++) dst[j * 4 + p] = acc[j][p];
    }
    __syncthreads();

    if (s == 0 && active) {
#pragma unroll
        for (int ps = 0; ps < 3; ps++) {
            const ull* src = part + ((ps * 2 + cg) * 28 + li) * 32;
#pragma unroll
            for (int j = 0; j < 8; j++)
#pragma unroll
                for (int p = 0; p < 4; p++)
                    acc[j][p] = add2(acc[j][p], src[j * 4 + p]);
        }

        int hp = (h0 + hh + 1) % 28;   // roll(+1) along H
#pragma unroll
        for (int j = 0; j < 8; j++) {
            int co = cg * 16 + 2 * j;
            float lo[4], hi[4];
#pragma unroll
            for (int p = 0; p < 4; p++) unpack2(acc[j][p], lo[p], hi[p]);
            float* o0 = out + (((size_t)b * 32 + co) * 28 + hp) * 28 + w0;
            float* o1 = o0 + 784;
            *(float4*)o0 = make_float4(lo[0], lo[1], lo[2], lo[3]);
            *(float4*)o1 = make_float4(hi[0], hi[1], hi[2], hi[3]);
        }
    }
}

extern "C" void kernel_launch(void* const* d_in, const int* in_sizes, int n_in,
                              void* d_out, int out_size) {
    const float* x = (const float*)d_in[0];
    const float* w = (const float*)d_in[1];
    float* out = (float*)d_out;

    cudaFuncSetAttribute(conv_kernel,
                         cudaFuncAttributeMaxDynamicSharedMemorySize, SMEM_BYTES);

    wT_kernel<<<48, 256>>>(w);
    conv_kernel<<<dim3(7, 128), NT, SMEM_BYTES>>>(x, out);
}